// round 10
// baseline (speedup 1.0000x reference)
#include <cuda_runtime.h>

#define EMBED   1024
#define EPB     8
#define NB      64
#define KTOP    2
#define SPLIT   8
#define CAP     2048

// ---------------------------------------------------------------------------
// Fused router. One block per (bucket, slice).
// Warp pass = 4 tokens. Dot accumulators live as vals[32] (= token*8+expert);
// a 31-shuffle reduce-scatter lands accumulator L fully-summed on lane L.
// Epilogue (softmax + top2 + write) runs data-parallel across all lanes.
// Output f32: out[0:ntok*K]=gid, out[ntok*K:2*ntok*K]=w.
// ---------------------------------------------------------------------------
__global__ __launch_bounds__(256, 2) void router_kernel(
    const float* __restrict__ h,
    const void*  __restrict__ op_raw,
    const float* __restrict__ key,
    float*       __restrict__ out,
    int ntok)
{
    __shared__ float          skey[EPB * EMBED];   // 32 KB
    __shared__ unsigned short slist[CAP];          // 4 KB
    __shared__ int            scount;
    __shared__ int            any_nz;

    const int bucket = blockIdx.x / SPLIT;
    const int slice  = blockIdx.x % SPLIT;
    const int tid    = threadIdx.x;
    const int wid    = tid >> 5;
    const int lane   = tid & 31;
    const unsigned FULL = 0xffffffffu;

    if (tid == 0) { scount = 0; any_nz = 0; }
    __syncthreads();

    // --- dtype probe: int64 LE op_id => odd 32-bit words all zero.
    {
        const int* op32 = (const int*)op_raw;
        if (tid < 64 && (2 * tid + 1) < ntok)
            if (op32[2 * tid + 1] != 0) atomicOr(&any_nz, 1);
    }

    // --- stage this bucket's raw keys (float4)
    const float4* kg = (const float4*)(key + (size_t)bucket * EPB * EMBED);
    float4*       ks = (float4*)skey;
    #pragma unroll
    for (int r = 0; r < 8; r++) ks[tid + 256 * r] = kg[tid + 256 * r];
    __syncthreads();

    const int is64 = any_nz ? 0 : 1;

    // --- scan contiguous token slice, collect matches
    {
        const int cands  = (ntok + SPLIT - 1) / SPLIT;
        const int tstart = slice * cands;
        const int tend   = (tstart + cands < ntok) ? (tstart + cands) : ntok;
        for (int t = tstart + tid; t < tend; t += 256) {
            long long v = is64 ? ((const long long*)op_raw)[t]
                               : (long long)((const int*)op_raw)[t];
            int b = (int)(v < 0 ? 0LL : (v > (NB - 1) ? (long long)(NB - 1) : v));
            if (b == bucket) {
                int p = atomicAdd(&scount, 1);
                if (p < CAP) slist[p] = (unsigned short)t;
            }
        }
    }

    // --- normalize key row `wid` in smem (8 warps = 8 rows)
    {
        float ss = 0.f;
        #pragma unroll
        for (int k = 0; k < 8; k++) {
            float4 v = ks[wid * 256 + k * 32 + lane];
            ss += v.x * v.x + v.y * v.y + v.z * v.z + v.w * v.w;
        }
        #pragma unroll
        for (int o = 16; o; o >>= 1) ss += __shfl_xor_sync(FULL, ss, o);
        float rn = 1.0f / fmaxf(sqrtf(ss), 1e-12f);
        #pragma unroll
        for (int k = 0; k < 8; k++) {
            float4 v = ks[wid * 256 + k * 32 + lane];
            v.x *= rn; v.y *= rn; v.z *= rn; v.w *= rn;
            ks[wid * 256 + k * 32 + lane] = v;
        }
    }
    __syncthreads();

    const int count = scount < CAP ? scount : CAP;
    const int btk   = ntok * KTOP;
    const float4* h4p = (const float4*)h;

    for (int base = wid * 4; base < count; base += 8 * 4) {
        const int t0 = (int)slist[(base + 0) < count ? base + 0 : base];
        const int t1 = (int)slist[(base + 1) < count ? base + 1 : base];
        const int t2 = (int)slist[(base + 2) < count ? base + 2 : base];
        const int t3 = (int)slist[(base + 3) < count ? base + 3 : base];

        float vals[32];
        float hh[4] = {0.f, 0.f, 0.f, 0.f};
        #pragma unroll
        for (int v = 0; v < 32; v++) vals[v] = 0.f;

        #pragma unroll
        for (int c = 0; c < 8; c++) {
            float4 hv0 = h4p[(size_t)t0 * (EMBED / 4) + c * 32 + lane];
            float4 hv1 = h4p[(size_t)t1 * (EMBED / 4) + c * 32 + lane];
            float4 hv2 = h4p[(size_t)t2 * (EMBED / 4) + c * 32 + lane];
            float4 hv3 = h4p[(size_t)t3 * (EMBED / 4) + c * 32 + lane];

            hh[0] += hv0.x * hv0.x + hv0.y * hv0.y + hv0.z * hv0.z + hv0.w * hv0.w;
            hh[1] += hv1.x * hv1.x + hv1.y * hv1.y + hv1.z * hv1.z + hv1.w * hv1.w;
            hh[2] += hv2.x * hv2.x + hv2.y * hv2.y + hv2.z * hv2.z + hv2.w * hv2.w;
            hh[3] += hv3.x * hv3.x + hv3.y * hv3.y + hv3.z * hv3.z + hv3.w * hv3.w;

            #pragma unroll
            for (int e = 0; e < EPB; e++) {
                float4 k4 = ks[e * (EMBED / 4) + c * 32 + lane];
                vals[0 * 8 + e] += hv0.x * k4.x + hv0.y * k4.y + hv0.z * k4.z + hv0.w * k4.w;
                vals[1 * 8 + e] += hv1.x * k4.x + hv1.y * k4.y + hv1.z * k4.z + hv1.w * k4.w;
                vals[2 * 8 + e] += hv2.x * k4.x + hv2.y * k4.y + hv2.z * k4.z + hv2.w * k4.w;
                vals[3 * 8 + e] += hv3.x * k4.x + hv3.y * k4.y + hv3.z * k4.z + hv3.w * k4.w;
            }
        }

        // Reduce-scatter: lane L ends with full sum of vals index L.
        #pragma unroll
        for (int s = 16; s >= 1; s >>= 1) {
            #pragma unroll
            for (int k = 0; k < s; k++) {
                bool  up   = (lane & s) != 0;
                float give = up ? vals[k] : vals[k + s];
                float keep = up ? vals[k + s] : vals[k];
                float recv = __shfl_xor_sync(FULL, give, s);
                vals[k] = keep + recv;
            }
        }

        // hh: full butterfly (every lane gets all 4 token norms)
        #pragma unroll
        for (int i = 0; i < 4; i++) {
            #pragma unroll
            for (int o = 16; o; o >>= 1) hh[i] += __shfl_xor_sync(FULL, hh[i], o);
        }

        // ---- data-parallel epilogue: lane L = (token L>>3, expert L&7)
        const int ti = lane >> 3;
        const int e  = lane & 7;
        const int idx = base + ti;
        const bool valid = idx < count;

        float hsel = (ti == 0) ? hh[0] : (ti == 1) ? hh[1] : (ti == 2) ? hh[2] : hh[3];
        float rh = 1.0f / fmaxf(sqrtf(hsel), 1e-12f);
        float sc = vals[0] * rh;                       // TAU = 1.0

        // softmax within 8-lane group
        float m = sc;
        #pragma unroll
        for (int o = 4; o; o >>= 1) m = fmaxf(m, __shfl_xor_sync(FULL, m, o));
        float p = __expf(sc - m);
        float Z = p;
        #pragma unroll
        for (int o = 4; o; o >>= 1) Z += __shfl_xor_sync(FULL, Z, o);

        // top-1 (max prob, lowest index on ties)
        float bv = p; int be = e;
        #pragma unroll
        for (int o = 4; o; o >>= 1) {
            float ov = __shfl_xor_sync(FULL, bv, o);
            int   oe = __shfl_xor_sync(FULL, be, o);
            if (ov > bv || (ov == bv && oe < be)) { bv = ov; be = oe; }
        }
        // top-2: exclude i1
        float p2 = (e == be) ? -1.f : p;
        float bv2 = p2; int be2 = e;
        #pragma unroll
        for (int o = 4; o; o >>= 1) {
            float ov = __shfl_xor_sync(FULL, bv2, o);
            int   oe = __shfl_xor_sync(FULL, be2, o);
            if (ov > bv2 || (ov == bv2 && oe < be2)) { bv2 = ov; be2 = oe; }
        }

        if (e == 0 && valid) {
            int tt = (int)slist[idx];
            float v1 = bv / Z, v2 = bv2 / Z;
            float ws = v1 + v2 + 1e-9f;
            ((float2*)out)[tt]         = make_float2((float)(bucket * EPB + be),
                                                     (float)(bucket * EPB + be2));
            ((float2*)(out + btk))[tt] = make_float2(v1 / ws, v2 / ws);
        }
    }
}

// ---------------------------------------------------------------------------
extern "C" void kernel_launch(void* const* d_in, const int* in_sizes, int n_in,
                              void* d_out, int out_size)
{
    const float* h   = (const float*)d_in[0];
    const void*  op  = d_in[1];
    const float* key = (const float*)d_in[2];
    float*       out = (float*)d_out;
    int ntok = in_sizes[1];

    router_kernel<<<NB * SPLIT, 256>>>(h, op, key, out, ntok);
}